// round 7
// baseline (speedup 1.0000x reference)
#include <cuda_runtime.h>
#include <cuda_bf16.h>
#include <cstdint>

// Per-token-group (G=128) dynamic fp8-range quantization.
// x: [M, N] stored as FLOAT32 on device (bf16-rounded values upcast by harness).
// y = clip(x/scale, +-448) fp32; scale = max(amax, 1e-4)/448 per group of 128.
// d_out layout: [y (M*N floats) || scale (M*N/128 floats)].

#define GROUP_SIZE 128
#define FP8_MAX 448.0f
#define AMAX_FLOOR 1e-4f

// Scratch if d_out has no room for scales (never write OOB).
__device__ float g_scale_scratch[1 << 20];

// One warp per group: 32 lanes x 4 fp32 = 128 elements.
__global__ void __launch_bounds__(256) quant_fp8_group_kernel(
    const float* __restrict__ x,
    float* __restrict__ y,
    float* __restrict__ scale,
    int num_groups)
{
    const int warp = threadIdx.x >> 5;             // 8 groups per 256-thread block
    const int lane = threadIdx.x & 31;
    const int g = blockIdx.x * 8 + warp;
    if (g >= num_groups) return;

    const size_t elem_base = (size_t)g * GROUP_SIZE + (size_t)lane * 4;

    // Load 4 fp32 (16 bytes, coalesced)
    float4 v = *reinterpret_cast<const float4*>(x + elem_base);

    // Local abs-max over 4 values
    float amax = fmaxf(fmaxf(fabsf(v.x), fabsf(v.y)),
                       fmaxf(fabsf(v.z), fabsf(v.w)));

    // Full-warp butterfly reduce (group == warp)
    #pragma unroll
    for (int k = 16; k >= 1; k >>= 1)
        amax = fmaxf(amax, __shfl_xor_sync(0xffffffffu, amax, k));

    amax = fmaxf(amax, AMAX_FLOOR);
    const float inv = FP8_MAX / amax;              // y = x * (448/amax)

    float4 o;
    o.x = fminf(fmaxf(v.x * inv, -FP8_MAX), FP8_MAX);
    o.y = fminf(fmaxf(v.y * inv, -FP8_MAX), FP8_MAX);
    o.z = fminf(fmaxf(v.z * inv, -FP8_MAX), FP8_MAX);
    o.w = fminf(fmaxf(v.w * inv, -FP8_MAX), FP8_MAX);

    // Store 4 fp32 (16 bytes, coalesced)
    *reinterpret_cast<float4*>(y + elem_base) = o;

    // One scale per group
    if (lane == 0) scale[g] = amax / FP8_MAX;
}

extern "C" void kernel_launch(void* const* d_in, const int* in_sizes, int n_in,
                              void* d_out, int out_size)
{
    const float* x = (const float*)d_in[0];
    const size_t total = (size_t)in_sizes[0];          // M * N (fp32 elements)
    const int num_groups = (int)(total / GROUP_SIZE);  // M * (N/128)

    float* base = (float*)d_out;
    float* y = base;                                   // y first (reference order)
    float* scale;

    if ((size_t)out_size >= total + (size_t)num_groups) {
        // Layout: [y (total) || scale (num_groups)] — scale fills the tail.
        scale = base + ((size_t)out_size - (size_t)num_groups);
    } else {
        // No room for scales in d_out: write them to device scratch (never OOB).
        void* sp = nullptr;
        cudaGetSymbolAddress(&sp, g_scale_scratch);
        scale = (float*)sp;
    }

    const int groups_per_block = 8;                    // 256 threads / 32 lanes
    const int grid = (num_groups + groups_per_block - 1) / groups_per_block;
    quant_fp8_group_kernel<<<grid, 256>>>(x, y, scale, num_groups);
}

// round 8
// speedup vs baseline: 1.0722x; 1.0722x over previous
#include <cuda_runtime.h>
#include <cuda_bf16.h>
#include <cstdint>

// Per-token-group (G=128) dynamic fp8-range quantization.
// x: [M, N] fp32 (bf16-rounded values upcast by harness).
// y = clip(x * 448/amax, +-448) fp32; scale = max(amax,1e-4)/448 per group.
// d_out layout: [y (M*N) || scale (M*N/128)] fp32.

#define GROUP_SIZE 128
#define FP8_MAX 448.0f
#define AMAX_FLOOR 1e-4f

__device__ float g_scale_scratch[1 << 20];  // fallback, never used in practice

__device__ __forceinline__ float max4abs(float4 v) {
    return fmaxf(fmaxf(fabsf(v.x), fabsf(v.y)), fmaxf(fabsf(v.z), fabsf(v.w)));
}

__device__ __forceinline__ float4 scale4(float4 v, float s) {
    float4 o;
    o.x = fminf(fmaxf(v.x * s, -FP8_MAX), FP8_MAX);
    o.y = fminf(fmaxf(v.y * s, -FP8_MAX), FP8_MAX);
    o.z = fminf(fmaxf(v.z * s, -FP8_MAX), FP8_MAX);
    o.w = fminf(fmaxf(v.w * s, -FP8_MAX), FP8_MAX);
    return o;
}

// One warp handles TWO groups (2 x 128 fp32 = 2 x 32 float4).
// Both 16B loads are issued back-to-back (MLP_p1 = 2) before any dependency.
// Warp abs-max via REDUX.MAX.U32 on the fabs bit pattern (monotone for >=0 floats).
__global__ void __launch_bounds__(256) quant_fp8_group_kernel(
    const float4* __restrict__ x4,
    float4* __restrict__ y4,
    float* __restrict__ scale,
    int num_groups)
{
    const int warp = threadIdx.x >> 5;
    const int lane = threadIdx.x & 31;
    const int g0 = (blockIdx.x * 8 + warp) * 2;     // first of two groups
    if (g0 >= num_groups) return;

    const size_t base = (size_t)g0 * 32 + (size_t)lane;  // in float4 units

    // Front-batched independent loads (two groups)
    float4 a = x4[base];
    float4 b = x4[base + 32];

    // Per-lane abs-max, then single-instruction warp reduce per group
    unsigned ra = __reduce_max_sync(0xffffffffu, __float_as_uint(max4abs(a)));
    unsigned rb = __reduce_max_sync(0xffffffffu, __float_as_uint(max4abs(b)));

    const float amaxA = fmaxf(__uint_as_float(ra), AMAX_FLOOR);
    const float amaxB = fmaxf(__uint_as_float(rb), AMAX_FLOOR);
    const float invA = FP8_MAX / amaxA;
    const float invB = FP8_MAX / amaxB;

    y4[base]      = scale4(a, invA);
    y4[base + 32] = scale4(b, invB);

    if (lane == 0) scale[g0] = amaxA / FP8_MAX;
    if (lane == 1 && g0 + 1 < num_groups) scale[g0 + 1] = amaxB / FP8_MAX;
}

extern "C" void kernel_launch(void* const* d_in, const int* in_sizes, int n_in,
                              void* d_out, int out_size)
{
    const float* x = (const float*)d_in[0];
    const size_t total = (size_t)in_sizes[0];          // M * N
    const int num_groups = (int)(total / GROUP_SIZE);

    float* base = (float*)d_out;
    float* scale;
    if ((size_t)out_size >= total + (size_t)num_groups) {
        scale = base + ((size_t)out_size - (size_t)num_groups);  // tail of d_out
    } else {
        void* sp = nullptr;
        cudaGetSymbolAddress(&sp, g_scale_scratch);
        scale = (float*)sp;
    }

    // 8 warps/block, 2 groups/warp -> 16 groups per block
    const int groups_per_block = 16;
    const int grid = (num_groups + groups_per_block - 1) / groups_per_block;
    quant_fp8_group_kernel<<<grid, 256>>>(
        (const float4*)x, (float4*)base, scale, num_groups);
}